// round 13
// baseline (speedup 1.0000x reference)
#include <cuda_runtime.h>
#include <cstdint>

#define B_    512
#define HW_   128
#define C1_   32
#define C2_   64

typedef unsigned long long u64;

// Padded intermediate h: [512][32][66][68], zero border. Valid data [1..64][1..64].
#define HP_R   66
#define HP_C   68
#define HP_CH  (HP_R * HP_C)          // 4488
__device__ float g_h[(size_t)B_ * C1_ * HP_CH];   // ~294 MB

// Pre-packed conv2 weights, duplicated pairs (w,w) for f32x2:
// [cc][oc][cil][10] u64; entries 0..8 = (w,w) prescaled, entry 9 = 0 pad.
__device__ u64 g_w2q[8 * C2_ * 4 * 10];
// Per-image partial sums from conv2 blocks: [b][4]
__device__ float g_part[B_ * 4];

// ---- packed f32x2 helpers -------------------------------------------------
__device__ __forceinline__ u64 pk2(float lo, float hi) {
    u64 r; asm("mov.b64 %0, {%1, %2};" : "=l"(r) : "f"(lo), "f"(hi)); return r;
}
__device__ __forceinline__ void fma2(u64& d, u64 a, u64 b) {
    asm("fma.rn.f32x2 %0, %1, %2, %0;" : "+l"(d) : "l"(a), "l"(b));
}
__device__ __forceinline__ void upk2(u64 v, float& lo, float& hi) {
    asm("mov.b64 {%0, %1}, %2;" : "=f"(lo), "=f"(hi) : "l"(v));
}

// ---- cp.async helpers -----------------------------------------------------
__device__ __forceinline__ uint32_t sptr(const void* p) {
    return (uint32_t)__cvta_generic_to_shared(p);
}
__device__ __forceinline__ void cpa16(uint32_t dst, const void* src) {
    asm volatile("cp.async.cg.shared.global [%0], [%1], 16;" :: "r"(dst), "l"(src));
}
__device__ __forceinline__ void cpa4(uint32_t dst, const void* src) {
    asm volatile("cp.async.ca.shared.global [%0], [%1], 4;" :: "r"(dst), "l"(src));
}
__device__ __forceinline__ void cpa_commit() {
    asm volatile("cp.async.commit_group;" ::: "memory");
}
template <int N>
__device__ __forceinline__ void cpa_wait() {
    asm volatile("cp.async.wait_group %0;" :: "n"(N) : "memory");
}

// ---------------------------------------------------------------------------
// Kernel 0: pre-pack conv2 weights as duplicated (w,w) u64 pairs
// ---------------------------------------------------------------------------
__global__ void conv2_prep(const float* __restrict__ w2,
                           const float* __restrict__ g2,
                           const float* __restrict__ v2)
{
    int i = blockIdx.x * 256 + threadIdx.x;
    if (i >= 8 * C2_ * 4 * 9) return;
    int cc  = i / (C2_ * 36);
    int rem = i % (C2_ * 36);
    int oc  = rem / 36;
    int k2  = rem % 36;
    int cil = k2 / 9, k = k2 % 9;
    float inv = g2[oc] * rsqrtf(v2[oc] + 1e-5f);
    float w = w2[oc * (C1_ * 9) + (cc * 4 + cil) * 9 + k] * inv;
    uint32_t bits = __float_as_uint(w);
    g_w2q[((cc * C2_ + oc) * 4 + cil) * 10 + k] = ((u64)bits << 32) | bits;
}

// ---------------------------------------------------------------------------
// Kernel 1: Conv(3->32, k3, s1, p1) + BN + ReLU + MaxPool2  (direct, R11 form)
// Grid (2, 4, 512), 256 thr: two horizontal pooled pixels per thread.
// ---------------------------------------------------------------------------
__global__ void __launch_bounds__(256) conv1_fused(
    const float* __restrict__ crops,
    const float* __restrict__ w1, const float* __restrict__ b1,
    const float* __restrict__ g1, const float* __restrict__ be1,
    const float* __restrict__ m1, const float* __restrict__ v1)
{
    __shared__ float s_in[3][34][68];
    __shared__ __align__(16) float s_w[C1_ * 36];
    __shared__ float s_bias[C1_];

    const int b   = blockIdx.z;
    const int cx0 = blockIdx.x * 64;
    const int cy0 = blockIdx.y * 32;
    const int t   = threadIdx.x;

    if (t < C1_) {
        float inv = g1[t] * rsqrtf(v1[t] + 1e-5f);
        s_bias[t] = be1[t] + (b1[t] - m1[t]) * inv;
    }
    for (int i = t; i < C1_ * 27; i += 256) {
        int oc = i / 27, k = i % 27;
        int ci = k / 9, ky = (k % 9) / 3, kx = k % 3;
        float inv = g1[oc] * rsqrtf(v1[oc] + 1e-5f);
        s_w[oc * 36 + ci * 12 + ky * 4 + kx] = w1[i] * inv;
    }

    const float* cb = crops + (size_t)b * 3 * HW_ * HW_;
    for (int i = t; i < 3 * 34 * 66; i += 256) {
        int ci = i / (34 * 66);
        int rem = i % (34 * 66);
        int r = rem / 66, c = rem % 66;
        int gr = cy0 - 1 + r, gc = cx0 - 1 + c;
        float v = 0.f;
        if (gr >= 0 && gr < HW_ && gc >= 0 && gc < HW_)
            v = cb[ci * HW_ * HW_ + gr * HW_ + gc];
        s_in[ci][r][c] = v;
    }
    __syncthreads();

    const int q  = t & 15;
    const int py = t >> 4;

    float p[3][4][6];
#pragma unroll
    for (int ci = 0; ci < 3; ci++)
#pragma unroll
        for (int r = 0; r < 4; r++) {
            const float* row = &s_in[ci][2 * py + r][4 * q];
            float4 v4 = *(const float4*)row;
            float2 v2 = *(const float2*)(row + 4);
            p[ci][r][0] = v4.x; p[ci][r][1] = v4.y; p[ci][r][2] = v4.z;
            p[ci][r][3] = v4.w; p[ci][r][4] = v2.x; p[ci][r][5] = v2.y;
        }

    const int oy = blockIdx.y * 16 + py;
    const int ox = blockIdx.x * 32 + 2 * q;
    float* hp = g_h + (size_t)b * C1_ * HP_CH + (oy + 1) * HP_C + (ox + 1);
    const float* wp = s_w;

    for (int oc = 0; oc < C1_; oc++, hp += HP_CH, wp += 36) {
        float a00 = 0.f, a01 = 0.f, a10 = 0.f, a11 = 0.f;
        float c00 = 0.f, c01 = 0.f, c10 = 0.f, c11 = 0.f;
        const float4* w4 = (const float4*)wp;
#pragma unroll
        for (int ci = 0; ci < 3; ci++)
#pragma unroll
            for (int ky = 0; ky < 3; ky++) {
                float4 w = w4[ci * 3 + ky];
                const float* r0 = p[ci][ky];
                const float* r1 = p[ci][ky + 1];
                a00 = fmaf(r0[0], w.x, a00);  a01 = fmaf(r0[1], w.x, a01);
                a10 = fmaf(r1[0], w.x, a10);  a11 = fmaf(r1[1], w.x, a11);
                c00 = fmaf(r0[2], w.x, c00);  c01 = fmaf(r0[3], w.x, c01);
                c10 = fmaf(r1[2], w.x, c10);  c11 = fmaf(r1[3], w.x, c11);
                a00 = fmaf(r0[1], w.y, a00);  a01 = fmaf(r0[2], w.y, a01);
                a10 = fmaf(r1[1], w.y, a10);  a11 = fmaf(r1[2], w.y, a11);
                c00 = fmaf(r0[3], w.y, c00);  c01 = fmaf(r0[4], w.y, c01);
                c10 = fmaf(r1[3], w.y, c10);  c11 = fmaf(r1[4], w.y, c11);
                a00 = fmaf(r0[2], w.z, a00);  a01 = fmaf(r0[3], w.z, a01);
                a10 = fmaf(r1[2], w.z, a10);  a11 = fmaf(r1[3], w.z, a11);
                c00 = fmaf(r0[4], w.z, c00);  c01 = fmaf(r0[5], w.z, c01);
                c10 = fmaf(r1[4], w.z, c10);  c11 = fmaf(r1[5], w.z, c11);
            }
        float bi = s_bias[oc];
        float mA = fmaxf(fmaxf(a00, a01), fmaxf(a10, a11)) + bi;
        float mB = fmaxf(fmaxf(c00, c01), fmaxf(c10, c11)) + bi;
        hp[0] = fmaxf(mA, 0.f);
        hp[1] = fmaxf(mB, 0.f);
    }
}

// ---------------------------------------------------------------------------
// Kernel 2: Conv(32->64, s2) + BN + Sigmoid + MaxPool2, cp.async + f32x2.
// Vertical output pairing: acc2[oc][j] = packed (row0, row1) for pooled col j.
// Stage layout (floats): in 4752 | wq 5120 (2560 u64) -> STG_F = 9872.
// ---------------------------------------------------------------------------
#define STG_F        9872
#define STG_W_OFF    4752
#define BI_OFF       (2 * STG_F)          // 19744
#define RED_OFF      (BI_OFF + 64)
#define CONV2_SMEM_BYTES  ((2 * STG_F + 64 + 8) * 4)

__global__ void __launch_bounds__(256, 2) conv2_fused(
    const float* __restrict__ b2, const float* __restrict__ g2,
    const float* __restrict__ be2, const float* __restrict__ m2,
    const float* __restrict__ v2,
    float* __restrict__ feat)
{
    extern __shared__ __align__(16) float sm[];

    const int b  = blockIdx.z;
    const int bx = blockIdx.x, by = blockIdx.y;
    const int t  = threadIdx.x;

    if (t < C2_) {
        float inv = g2[t] * rsqrtf(v2[t] + 1e-5f);
        sm[BI_OFF + t] = be2[t] + (b2[t] - m2[t]) * inv;
    }

    const float* hp = g_h + (size_t)b * C1_ * HP_CH + (32 * by) * HP_C + (32 * bx);
    const uint32_t sm_u32 = sptr(sm);

    auto issue = [&](int cc, int p) {
        const uint32_t base = sm_u32 + (uint32_t)(p * STG_F) * 4u;
        for (int i = t; i < 4 * 33 * 9; i += 256) {
            int ch  = i / 297;
            int rem = i - ch * 297;
            int r   = rem / 9;
            int s   = rem - r * 9;
            const float* src = hp + (cc * 4 + ch) * HP_CH + r * HP_C;
            uint32_t dst = base + (uint32_t)((ch * 33 + r) * 36) * 4u;
            if (s < 8) cpa16(dst + 16u * s, src + 4 * s);
            else       cpa4(dst + 128u, src + 32);
        }
        // weights: 2560 u64 = 1280 x 16B
        const float4* ws = (const float4*)(g_w2q + (size_t)cc * (C2_ * 40));
        const uint32_t wb = base + STG_W_OFF * 4u;
        for (int i = t; i < 1280; i += 256)
            cpa16(wb + 16u * i, ws + i);
        cpa_commit();
    };

    const int pix = t & 63, grp = t >> 6;      // grp 0..3 -> 16 oc each
    const int px = pix & 7, py = pix >> 3;

    u64 acc2[16][2];                           // [oc][pooled col], (row0,row1)
#pragma unroll
    for (int i = 0; i < 16; i++) { acc2[i][0] = 0ull; acc2[i][1] = 0ull; }

    issue(0, 0);

    for (int cc = 0; cc < 8; cc++) {
        const int cur = cc & 1;
        if (cc < 7) { issue(cc + 1, cur ^ 1); cpa_wait<1>(); }
        else        { cpa_wait<0>(); }
        __syncthreads();

        const float* sin = sm + cur * STG_F;
        const u64*  swq = (const u64*)(sin + STG_W_OFF);

#pragma unroll
        for (int cil = 0; cil < 4; cil++) {
            const float* rowb = sin + (cil * 33 + 4 * py) * 36 + 4 * px;

            // Load rows pairwise, pack P[ky][c] = (row[ky][c], row[ky+2][c])
            u64 P[3][5];
            {
                float ra[5], rb[5];
                auto ldrow = [&](int r, float* d) {
                    float4 v4 = *(const float4*)(rowb + r * 36);
                    d[0] = v4.x; d[1] = v4.y; d[2] = v4.z; d[3] = v4.w;
                    d[4] = rowb[r * 36 + 4];
                };
                ldrow(0, ra); ldrow(2, rb);
#pragma unroll
                for (int c = 0; c < 5; c++) P[0][c] = pk2(ra[c], rb[c]);
                ldrow(4, ra);
#pragma unroll
                for (int c = 0; c < 5; c++) P[2][c] = pk2(rb[c], ra[c]);
                ldrow(1, ra); ldrow(3, rb);
#pragma unroll
                for (int c = 0; c < 5; c++) P[1][c] = pk2(ra[c], rb[c]);
            }

#pragma unroll
            for (int oc = 0; oc < 16; oc++) {
                const u64* wq = swq + (size_t)((grp * 16 + oc) * 4 + cil) * 10;
                const ulonglong2* wv = (const ulonglong2*)wq;
                ulonglong2 w01 = wv[0], w23 = wv[1], w45 = wv[2], w67 = wv[3];
                u64 w8 = wq[8];
                // ky=0: w0,w1,w2 ; ky=1: w3,w4,w5 ; ky=2: w6,w7,w8
                fma2(acc2[oc][0], P[0][0], w01.x); fma2(acc2[oc][1], P[0][2], w01.x);
                fma2(acc2[oc][0], P[0][1], w01.y); fma2(acc2[oc][1], P[0][3], w01.y);
                fma2(acc2[oc][0], P[0][2], w23.x); fma2(acc2[oc][1], P[0][4], w23.x);
                fma2(acc2[oc][0], P[1][0], w23.y); fma2(acc2[oc][1], P[1][2], w23.y);
                fma2(acc2[oc][0], P[1][1], w45.x); fma2(acc2[oc][1], P[1][3], w45.x);
                fma2(acc2[oc][0], P[1][2], w45.y); fma2(acc2[oc][1], P[1][4], w45.y);
                fma2(acc2[oc][0], P[2][0], w67.x); fma2(acc2[oc][1], P[2][2], w67.x);
                fma2(acc2[oc][0], P[2][1], w67.y); fma2(acc2[oc][1], P[2][3], w67.y);
                fma2(acc2[oc][0], P[2][2], w8);    fma2(acc2[oc][1], P[2][4], w8);
            }
        }
        __syncthreads();
    }

    // Epilogue: unpack -> max-pool -> +bias -> sigmoid; score partial
    const int oy = by * 8 + py, ox = bx * 8 + px;
    float* fb = feat + (size_t)b * C2_ * 16 * 16;
    float lsum = 0.f;
#pragma unroll
    for (int oc = 0; oc < 16; oc++) {
        int c = grp * 16 + oc;
        float v00, v10, v01, v11;
        upk2(acc2[oc][0], v00, v10);
        upk2(acc2[oc][1], v01, v11);
        float m = fmaxf(fmaxf(v00, v01), fmaxf(v10, v11));
        float v = m + sm[BI_OFF + c];
        float sig = 1.f / (1.f + __expf(-v));
        fb[c * 256 + oy * 16 + ox] = sig;
        lsum += sig;
    }
#pragma unroll
    for (int o = 16; o > 0; o >>= 1) lsum += __shfl_down_sync(0xffffffffu, lsum, o);
    if ((t & 31) == 0) sm[RED_OFF + (t >> 5)] = lsum;
    __syncthreads();
    if (t < 8) {
        lsum = sm[RED_OFF + t];
#pragma unroll
        for (int o = 4; o > 0; o >>= 1) lsum += __shfl_down_sync(0xffu, lsum, o);
        if (t == 0) g_part[b * 4 + by * 2 + bx] = lsum;
    }
}

// ---------------------------------------------------------------------------
// Kernel 3: final score: sum 4 partials per image -> scores + detected
// ---------------------------------------------------------------------------
__global__ void __launch_bounds__(256) score_final(
    float* __restrict__ scores, float* __restrict__ detected)
{
    int b = blockIdx.x * 256 + threadIdx.x;
    if (b >= B_) return;
    const float* p = g_part + b * 4;
    float s = (p[0] + p[1]) + (p[2] + p[3]);
    float sc = s * (1.f / 16384.f);
    scores[b]   = sc;
    detected[b] = (sc >= 0.55f) ? 1.f : 0.f;
}

// ---------------------------------------------------------------------------
extern "C" void kernel_launch(void* const* d_in, const int* in_sizes, int n_in,
                              void* d_out, int out_size)
{
    const float* crops = (const float*)d_in[0];
    const float* w1  = (const float*)d_in[1];
    const float* b1  = (const float*)d_in[2];
    const float* g1  = (const float*)d_in[3];
    const float* be1 = (const float*)d_in[4];
    const float* m1  = (const float*)d_in[5];
    const float* v1  = (const float*)d_in[6];
    const float* w2  = (const float*)d_in[7];
    const float* b2  = (const float*)d_in[8];
    const float* g2  = (const float*)d_in[9];
    const float* be2 = (const float*)d_in[10];
    const float* m2  = (const float*)d_in[11];
    const float* v2  = (const float*)d_in[12];

    float* out      = (float*)d_out;
    float* feat     = out;                                   // 512*64*16*16
    float* scores   = out + (size_t)B_ * C2_ * 16 * 16;      // +512
    float* detected = scores + B_;                           // +512

    static int smem_set = 0;
    if (!smem_set) {
        cudaFuncSetAttribute(conv2_fused,
                             cudaFuncAttributeMaxDynamicSharedMemorySize,
                             CONV2_SMEM_BYTES);
        smem_set = 1;
    }

    conv2_prep<<<72, 256>>>(w2, g2, v2);
    conv1_fused<<<dim3(2, 4, B_), 256>>>(crops, w1, b1, g1, be1, m1, v1);
    conv2_fused<<<dim3(2, 2, B_), 256, CONV2_SMEM_BYTES>>>(b2, g2, be2, m2, v2, feat);
    score_final<<<2, 256>>>(scores, detected);
}

// round 14
// speedup vs baseline: 1.2999x; 1.2999x over previous
#include <cuda_runtime.h>
#include <cstdint>

#define B_    512
#define HW_   128
#define C1_   32
#define C2_   64

// Padded intermediate h: [512][32][66][68], zero border. Valid data [1..64][1..64].
#define HP_R   66
#define HP_C   68
#define HP_CH  (HP_R * HP_C)          // 4488
__device__ float g_h[(size_t)B_ * C1_ * HP_CH];   // ~294 MB

// Pre-packed conv2 weights: [cc][oc][cil][ky][4], pre-scaled by BN scale.
__device__ float g_w2p[8 * 3072];
// Per-image partial sums from conv2 blocks: [b][4]
__device__ float g_part[B_ * 4];

// ---- cp.async helpers -----------------------------------------------------
__device__ __forceinline__ uint32_t sptr(const void* p) {
    return (uint32_t)__cvta_generic_to_shared(p);
}
__device__ __forceinline__ void cpa16(uint32_t dst, const void* src) {
    asm volatile("cp.async.cg.shared.global [%0], [%1], 16;" :: "r"(dst), "l"(src));
}
__device__ __forceinline__ void cpa4(uint32_t dst, const void* src) {
    asm volatile("cp.async.ca.shared.global [%0], [%1], 4;" :: "r"(dst), "l"(src));
}
__device__ __forceinline__ void cpa_commit() {
    asm volatile("cp.async.commit_group;" ::: "memory");
}
template <int N>
__device__ __forceinline__ void cpa_wait() {
    asm volatile("cp.async.wait_group %0;" :: "n"(N) : "memory");
}

// ---------------------------------------------------------------------------
// Kernel 0: pre-pack conv2 weights (18432 items)
// ---------------------------------------------------------------------------
__global__ void conv2_prep(const float* __restrict__ w2,
                           const float* __restrict__ g2,
                           const float* __restrict__ v2)
{
    int i = blockIdx.x * 256 + threadIdx.x;
    if (i >= 8 * C2_ * 36) return;
    int cc  = i / (C2_ * 36);
    int rem = i % (C2_ * 36);
    int oc  = rem / 36;
    int k2  = rem % 36;
    int cil = k2 / 9, k = k2 % 9;
    int ky = k / 3, kx = k % 3;
    float inv = g2[oc] * rsqrtf(v2[oc] + 1e-5f);
    g_w2p[cc * 3072 + oc * 48 + cil * 12 + ky * 4 + kx] =
        w2[oc * (C1_ * 9) + (cc * 4 + cil) * 9 + k] * inv;
}

// ---------------------------------------------------------------------------
// Kernel 1: Conv(3->32, k3, s1, p1) + BN + ReLU + MaxPool2  (direct)
// Grid (2, 4, 512), 256 thr. Two horizontal pooled pixels per thread.
// launch_bounds(256,3): target ~85 regs -> 24 warps/SM.
// ---------------------------------------------------------------------------
__global__ void __launch_bounds__(256, 3) conv1_fused(
    const float* __restrict__ crops,
    const float* __restrict__ w1, const float* __restrict__ b1,
    const float* __restrict__ g1, const float* __restrict__ be1,
    const float* __restrict__ m1, const float* __restrict__ v1)
{
    __shared__ float s_in[3][34][68];
    __shared__ __align__(16) float s_w[C1_ * 36];
    __shared__ float s_bias[C1_];

    const int b   = blockIdx.z;
    const int cx0 = blockIdx.x * 64;
    const int cy0 = blockIdx.y * 32;
    const int t   = threadIdx.x;

    if (t < C1_) {
        float inv = g1[t] * rsqrtf(v1[t] + 1e-5f);
        s_bias[t] = be1[t] + (b1[t] - m1[t]) * inv;
    }
    for (int i = t; i < C1_ * 27; i += 256) {
        int oc = i / 27, k = i % 27;
        int ci = k / 9, ky = (k % 9) / 3, kx = k % 3;
        float inv = g1[oc] * rsqrtf(v1[oc] + 1e-5f);
        s_w[oc * 36 + ci * 12 + ky * 4 + kx] = w1[i] * inv;
    }

    const float* cb = crops + (size_t)b * 3 * HW_ * HW_;
    for (int i = t; i < 3 * 34 * 66; i += 256) {
        int ci = i / (34 * 66);
        int rem = i % (34 * 66);
        int r = rem / 66, c = rem % 66;
        int gr = cy0 - 1 + r, gc = cx0 - 1 + c;
        float v = 0.f;
        if (gr >= 0 && gr < HW_ && gc >= 0 && gc < HW_)
            v = cb[ci * HW_ * HW_ + gr * HW_ + gc];
        s_in[ci][r][c] = v;
    }
    __syncthreads();

    const int q  = t & 15;          // pooled col-pair index (covers 2q, 2q+1)
    const int py = t >> 4;          // pooled row in tile (0..15)

    float p[3][4][6];
#pragma unroll
    for (int ci = 0; ci < 3; ci++)
#pragma unroll
        for (int r = 0; r < 4; r++) {
            const float* row = &s_in[ci][2 * py + r][4 * q];
            float4 v4 = *(const float4*)row;
            float2 v2 = *(const float2*)(row + 4);
            p[ci][r][0] = v4.x; p[ci][r][1] = v4.y; p[ci][r][2] = v4.z;
            p[ci][r][3] = v4.w; p[ci][r][4] = v2.x; p[ci][r][5] = v2.y;
        }

    const int oy = blockIdx.y * 16 + py;
    const int ox = blockIdx.x * 32 + 2 * q;
    float* hp = g_h + (size_t)b * C1_ * HP_CH + (oy + 1) * HP_C + (ox + 1);
    const float* wp = s_w;

    for (int oc = 0; oc < C1_; oc++, hp += HP_CH, wp += 36) {
        float a00 = 0.f, a01 = 0.f, a10 = 0.f, a11 = 0.f;
        float c00 = 0.f, c01 = 0.f, c10 = 0.f, c11 = 0.f;
        const float4* w4 = (const float4*)wp;
#pragma unroll
        for (int ci = 0; ci < 3; ci++)
#pragma unroll
            for (int ky = 0; ky < 3; ky++) {
                float4 w = w4[ci * 3 + ky];
                const float* r0 = p[ci][ky];
                const float* r1 = p[ci][ky + 1];
                a00 = fmaf(r0[0], w.x, a00);  a01 = fmaf(r0[1], w.x, a01);
                a10 = fmaf(r1[0], w.x, a10);  a11 = fmaf(r1[1], w.x, a11);
                c00 = fmaf(r0[2], w.x, c00);  c01 = fmaf(r0[3], w.x, c01);
                c10 = fmaf(r1[2], w.x, c10);  c11 = fmaf(r1[3], w.x, c11);
                a00 = fmaf(r0[1], w.y, a00);  a01 = fmaf(r0[2], w.y, a01);
                a10 = fmaf(r1[1], w.y, a10);  a11 = fmaf(r1[2], w.y, a11);
                c00 = fmaf(r0[3], w.y, c00);  c01 = fmaf(r0[4], w.y, c01);
                c10 = fmaf(r1[3], w.y, c10);  c11 = fmaf(r1[4], w.y, c11);
                a00 = fmaf(r0[2], w.z, a00);  a01 = fmaf(r0[3], w.z, a01);
                a10 = fmaf(r1[2], w.z, a10);  a11 = fmaf(r1[3], w.z, a11);
                c00 = fmaf(r0[4], w.z, c00);  c01 = fmaf(r0[5], w.z, c01);
                c10 = fmaf(r1[4], w.z, c10);  c11 = fmaf(r1[5], w.z, c11);
            }
        float bi = s_bias[oc];
        float mA = fmaxf(fmaxf(a00, a01), fmaxf(a10, a11)) + bi;
        float mB = fmaxf(fmaxf(c00, c01), fmaxf(c10, c11)) + bi;
        hp[0] = fmaxf(mA, 0.f);
        hp[1] = fmaxf(mB, 0.f);
    }
}

// ---------------------------------------------------------------------------
// Kernel 2: Conv(32->64, s2) + BN + Sigmoid + MaxPool2 (R8 body, cp.async)
// ---------------------------------------------------------------------------
#define STG_F        7824
#define STG_W_OFF    4752
#define BI_OFF       15648
#define RED_OFF      (BI_OFF + 64)
#define CONV2_SMEM_BYTES  ((2 * STG_F + 64 + 8) * 4)

__global__ void __launch_bounds__(256) conv2_fused(
    const float* __restrict__ b2, const float* __restrict__ g2,
    const float* __restrict__ be2, const float* __restrict__ m2,
    const float* __restrict__ v2,
    float* __restrict__ feat)
{
    extern __shared__ __align__(16) float sm[];

    const int b  = blockIdx.z;
    const int bx = blockIdx.x, by = blockIdx.y;
    const int t  = threadIdx.x;

    if (t < C2_) {
        float inv = g2[t] * rsqrtf(v2[t] + 1e-5f);
        sm[BI_OFF + t] = be2[t] + (b2[t] - m2[t]) * inv;
    }

    const float* hp = g_h + (size_t)b * C1_ * HP_CH + (32 * by) * HP_C + (32 * bx);
    const uint32_t sm_u32 = sptr(sm);

    auto issue = [&](int cc, int p) {
        const uint32_t base = sm_u32 + (uint32_t)(p * STG_F) * 4u;
        for (int i = t; i < 4 * 33 * 9; i += 256) {
            int ch  = i / 297;
            int rem = i - ch * 297;
            int r   = rem / 9;
            int s   = rem - r * 9;
            const float* src = hp + (cc * 4 + ch) * HP_CH + r * HP_C;
            uint32_t dst = base + (uint32_t)((ch * 33 + r) * 36) * 4u;
            if (s < 8) cpa16(dst + 16u * s, src + 4 * s);
            else       cpa4(dst + 128u, src + 32);
        }
        const float4* ws = (const float4*)(g_w2p + cc * 3072);
        const uint32_t wb = base + STG_W_OFF * 4u;
        for (int i = t; i < 768; i += 256)
            cpa16(wb + 16u * i, ws + i);
        cpa_commit();
    };

    const int pix = t & 63, grp = t >> 6;
    const int px = pix & 7, py = pix >> 3;

    float acc[16][2][2];
#pragma unroll
    for (int i = 0; i < 16; i++) {
        acc[i][0][0] = 0.f; acc[i][0][1] = 0.f;
        acc[i][1][0] = 0.f; acc[i][1][1] = 0.f;
    }

    issue(0, 0);

    for (int cc = 0; cc < 8; cc++) {
        const int cur = cc & 1;
        if (cc < 7) { issue(cc + 1, cur ^ 1); cpa_wait<1>(); }
        else        { cpa_wait<0>(); }
        __syncthreads();

        const float* sin = sm + cur * STG_F;
        const float* sw  = sin + STG_W_OFF;

#pragma unroll
        for (int cil = 0; cil < 4; cil++) {
            const float* row = sin + (cil * 33 + 4 * py) * 36 + 4 * px;
            float p[5][5];
#pragma unroll
            for (int r = 0; r < 5; r++) {
                float4 v4 = *(const float4*)(row + r * 36);
                p[r][0] = v4.x; p[r][1] = v4.y; p[r][2] = v4.z; p[r][3] = v4.w;
                p[r][4] = row[r * 36 + 4];
            }

#pragma unroll
            for (int oc = 0; oc < 16; oc++) {
                const float4* w4 = (const float4*)(sw + (grp * 16 + oc) * 48 + cil * 12);
#pragma unroll
                for (int ky = 0; ky < 3; ky++) {
                    float4 w = w4[ky];
                    acc[oc][0][0] = fmaf(p[ky    ][0], w.x, acc[oc][0][0]);
                    acc[oc][0][1] = fmaf(p[ky    ][2], w.x, acc[oc][0][1]);
                    acc[oc][1][0] = fmaf(p[ky + 2][0], w.x, acc[oc][1][0]);
                    acc[oc][1][1] = fmaf(p[ky + 2][2], w.x, acc[oc][1][1]);
                    acc[oc][0][0] = fmaf(p[ky    ][1], w.y, acc[oc][0][0]);
                    acc[oc][0][1] = fmaf(p[ky    ][3], w.y, acc[oc][0][1]);
                    acc[oc][1][0] = fmaf(p[ky + 2][1], w.y, acc[oc][1][0]);
                    acc[oc][1][1] = fmaf(p[ky + 2][3], w.y, acc[oc][1][1]);
                    acc[oc][0][0] = fmaf(p[ky    ][2], w.z, acc[oc][0][0]);
                    acc[oc][0][1] = fmaf(p[ky    ][4], w.z, acc[oc][0][1]);
                    acc[oc][1][0] = fmaf(p[ky + 2][2], w.z, acc[oc][1][0]);
                    acc[oc][1][1] = fmaf(p[ky + 2][4], w.z, acc[oc][1][1]);
                }
            }
        }
        __syncthreads();
    }

    const int oy = by * 8 + py, ox = bx * 8 + px;
    float* fb = feat + (size_t)b * C2_ * 16 * 16;
    float lsum = 0.f;
#pragma unroll
    for (int oc = 0; oc < 16; oc++) {
        int c = grp * 16 + oc;
        float m = fmaxf(fmaxf(acc[oc][0][0], acc[oc][0][1]),
                        fmaxf(acc[oc][1][0], acc[oc][1][1]));
        float v = m + sm[BI_OFF + c];
        float sig = 1.f / (1.f + __expf(-v));
        fb[c * 256 + oy * 16 + ox] = sig;
        lsum += sig;
    }
#pragma unroll
    for (int o = 16; o > 0; o >>= 1) lsum += __shfl_down_sync(0xffffffffu, lsum, o);
    if ((t & 31) == 0) sm[RED_OFF + (t >> 5)] = lsum;
    __syncthreads();
    if (t < 8) {
        lsum = sm[RED_OFF + t];
#pragma unroll
        for (int o = 4; o > 0; o >>= 1) lsum += __shfl_down_sync(0xffu, lsum, o);
        if (t == 0) g_part[b * 4 + by * 2 + bx] = lsum;
    }
}

// ---------------------------------------------------------------------------
// Kernel 3: final score: sum 4 partials per image -> scores + detected
// ---------------------------------------------------------------------------
__global__ void __launch_bounds__(256) score_final(
    float* __restrict__ scores, float* __restrict__ detected)
{
    int b = blockIdx.x * 256 + threadIdx.x;
    if (b >= B_) return;
    const float* p = g_part + b * 4;
    float s = (p[0] + p[1]) + (p[2] + p[3]);
    float sc = s * (1.f / 16384.f);
    scores[b]   = sc;
    detected[b] = (sc >= 0.55f) ? 1.f : 0.f;
}

// ---------------------------------------------------------------------------
extern "C" void kernel_launch(void* const* d_in, const int* in_sizes, int n_in,
                              void* d_out, int out_size)
{
    const float* crops = (const float*)d_in[0];
    const float* w1  = (const float*)d_in[1];
    const float* b1  = (const float*)d_in[2];
    const float* g1  = (const float*)d_in[3];
    const float* be1 = (const float*)d_in[4];
    const float* m1  = (const float*)d_in[5];
    const float* v1  = (const float*)d_in[6];
    const float* w2  = (const float*)d_in[7];
    const float* b2  = (const float*)d_in[8];
    const float* g2  = (const float*)d_in[9];
    const float* be2 = (const float*)d_in[10];
    const float* m2  = (const float*)d_in[11];
    const float* v2  = (const float*)d_in[12];

    float* out      = (float*)d_out;
    float* feat     = out;                                   // 512*64*16*16
    float* scores   = out + (size_t)B_ * C2_ * 16 * 16;      // +512
    float* detected = scores + B_;                           // +512

    static int smem_set = 0;
    if (!smem_set) {
        cudaFuncSetAttribute(conv2_fused,
                             cudaFuncAttributeMaxDynamicSharedMemorySize,
                             CONV2_SMEM_BYTES);
        smem_set = 1;
    }

    conv2_prep<<<72, 256>>>(w2, g2, v2);
    conv1_fused<<<dim3(2, 4, B_), 256>>>(crops, w1, b1, g1, be1, m1, v1);
    conv2_fused<<<dim3(2, 2, B_), 256, CONV2_SMEM_BYTES>>>(b2, g2, be2, m2, v2, feat);
    score_final<<<2, 256>>>(scores, detected);
}